// round 4
// baseline (speedup 1.0000x reference)
#include <cuda_runtime.h>
#include <cuda_fp16.h>
#include <cstdint>
#include <math.h>

#define NEXP 8
#define NTOK 4096
#define DM   1024
#define DFF  4096
#define ROWS_CAP 9216
#define MAXT 72

// ---------------- device scratch (no allocations allowed) ----------------
__device__ __half g_xh[(size_t)NTOK * DM];        // x in fp16              (8 MB)
__device__ __half g_act[(size_t)ROWS_CAP * DFF];  // silu(gate)*up          (75.5 MB)
__device__ float  g_y[(size_t)ROWS_CAP * DM];     // coef * (act@W2)        (37.7 MB)
__device__ int    g_rowtok[ROWS_CAP];
__device__ float  g_rowcoef[ROWS_CAP];
__device__ int    g_tok2row[NTOK * 2];
__device__ int    g_tile_expert[MAXT];
__device__ int    g_ntiles;

// ---------------- prep: x -> fp16 ----------------
__global__ void prep_kernel(const float4* __restrict__ x4) {
    int i = blockIdx.x * 256 + threadIdx.x;   // 1M float4
    float4 v = x4[i];
    __half2 h0 = __floats2half2_rn(v.x, v.y);
    __half2 h1 = __floats2half2_rn(v.z, v.w);
    uint2 u;
    u.x = *(const uint32_t*)&h0;
    u.y = *(const uint32_t*)&h1;
    ((uint2*)g_xh)[i] = u;
}

// ---------------- routing: top-2 of 8, renorm, compact per-expert rows ----------------
__global__ void __launch_bounds__(1024) routing_kernel(const float* __restrict__ gating) {
    __shared__ int cnt[NEXP], off[NEXP], cur[NEXP];
    __shared__ int nrows_s;
    int t = threadIdx.x;
    if (t < NEXP) { cnt[t] = 0; cur[t] = 0; }
    __syncthreads();
    int be0[4], be1[4]; float bc0[4], bc1[4];
    for (int i = 0; i < 4; i++) {
        int tok = t * 4 + i;
        float l[NEXP]; float m = -3e38f;
#pragma unroll
        for (int e = 0; e < NEXP; e++) { l[e] = gating[tok * NEXP + e]; m = fmaxf(m, l[e]); }
        int b0 = 0; float v0 = l[0];
#pragma unroll
        for (int e = 1; e < NEXP; e++) if (l[e] > v0) { v0 = l[e]; b0 = e; }
        int b1 = -1; float v1 = -3e38f;
#pragma unroll
        for (int e = 0; e < NEXP; e++) if (e != b0 && l[e] > v1) { v1 = l[e]; b1 = e; }
        float p0 = __expf(v0 - m), p1 = __expf(v1 - m);
        float inv = 1.f / (p0 + p1);
        be0[i] = b0; bc0[i] = p0 * inv;
        be1[i] = b1; bc1[i] = p1 * inv;
        atomicAdd(&cnt[b0], 1); atomicAdd(&cnt[b1], 1);
    }
    __syncthreads();
    if (t == 0) {
        int o = 0;
        for (int e = 0; e < NEXP; e++) {
            off[e] = o;
            int p = (cnt[e] + 127) & ~127;
            for (int j = 0; j < (p >> 7); j++) g_tile_expert[(o >> 7) + j] = e;
            o += p;
        }
        g_ntiles = o >> 7;
        nrows_s = o;
    }
    __syncthreads();
    int nr = nrows_s;
    for (int r = t; r < nr; r += 1024) { g_rowtok[r] = 0; g_rowcoef[r] = 0.f; }
    __syncthreads();
    for (int i = 0; i < 4; i++) {
        int tok = t * 4 + i;
        int p0 = off[be0[i]] + atomicAdd(&cur[be0[i]], 1);
        g_rowtok[p0] = tok; g_rowcoef[p0] = bc0[i];
        g_tok2row[tok * 2 + 0] = p0;
        int p1 = off[be1[i]] + atomicAdd(&cur[be1[i]], 1);
        g_rowtok[p1] = tok; g_rowcoef[p1] = bc1[i];
        g_tok2row[tok * 2 + 1] = p1;
    }
}

// ---------------- warp MMA / ldmatrix primitives ----------------
__device__ __forceinline__ void mma16816(float* c, const uint32_t* a, const uint32_t* b) {
    asm volatile(
        "mma.sync.aligned.m16n8k16.row.col.f32.f16.f16.f32 "
        "{%0,%1,%2,%3}, {%4,%5,%6,%7}, {%8,%9}, {%0,%1,%2,%3};\n"
        : "+f"(c[0]), "+f"(c[1]), "+f"(c[2]), "+f"(c[3])
        : "r"(a[0]), "r"(a[1]), "r"(a[2]), "r"(a[3]), "r"(b[0]), "r"(b[1]));
}
__device__ __forceinline__ void ldsm4(uint32_t* r, uint32_t a) {
    asm volatile("ldmatrix.sync.aligned.m8n8.x4.shared.b16 {%0,%1,%2,%3}, [%4];"
        : "=r"(r[0]), "=r"(r[1]), "=r"(r[2]), "=r"(r[3]) : "r"(a));
}
__device__ __forceinline__ void ldsm4t(uint32_t* r, uint32_t a) {
    asm volatile("ldmatrix.sync.aligned.m8n8.x4.trans.shared.b16 {%0,%1,%2,%3}, [%4];"
        : "=r"(r[0]), "=r"(r[1]), "=r"(r[2]), "=r"(r[3]) : "r"(a));
}
__device__ __forceinline__ uint32_t smem_u32(const void* p) {
    uint32_t a;
    asm("{ .reg .u64 t; cvta.to.shared.u64 t, %1; cvt.u32.u64 %0, t; }" : "=r"(a) : "l"(p));
    return a;
}

// ============ unified GEMM: G1 = x@W1 + silu*up -> g_act ; !G1 = act@W2 -> g_y ============
// CTA: 128 rows x 128 smem n-cols, K-chunk 32, double-buffered.
// A smem [128][40] halves; B smem k-major [32][136] halves (dequant STS.64 conflict-free,
// fragments via ldmatrix.trans).
template<bool G1>
__global__ void __launch_bounds__(256, 2) gemm_kernel(const int* __restrict__ wq,
                                                      const float* __restrict__ ws) {
    constexpr int KTOT = G1 ? DM : DFF;
    constexpr int NW   = G1 ? 2 * DFF : DM;     // gmem row width (n stride)
    constexpr int NC   = KTOT / 32;

    const int mt = blockIdx.x;                   // mt fastest -> L2 weight sharing
    if (mt >= g_ntiles) return;
    const int e      = g_tile_expert[mt];
    const int row0   = mt << 7;
    const int base_n = G1 ? (blockIdx.y << 6) : (blockIdx.y << 7);

    __shared__ __align__(16) __half sA[2][128 * 40];
    __shared__ __align__(16) __half sB[2][32 * 136];
    __shared__ int   sTok[128];
    __shared__ float sCoef[128];

    const int tid = threadIdx.x;
    if (tid < 128) { sTok[tid] = g_rowtok[row0 + tid]; sCoef[tid] = g_rowcoef[row0 + tid]; }
    __syncthreads();

    const int lane = tid & 31, warp = tid >> 5;
    const int wm = warp & 1, wn = warp >> 1;      // 2 x 4 warp grid (64m x n-pattern)
    const int qr = lane >> 2, qc = (lane & 3) << 1;
    const int lrow = (lane & 7) + (((lane >> 3) & 1) << 3);
    const int lcol = (lane >> 4) << 3;

    float acc[4][4][4];
#pragma unroll
    for (int a = 0; a < 4; a++)
#pragma unroll
        for (int b = 0; b < 4; b++)
#pragma unroll
            for (int k = 0; k < 4; k++) acc[a][b][k] = 0.f;

    // ---- staging maps ----
    const int arow = tid >> 1, aseg = tid & 1;
    const __half* Asrc = G1 ? (g_xh + (size_t)sTok[arow] * DM)
                            : (g_act + (size_t)(row0 + arow) * DFF);
    int bk[4], bcol[4], bsm[4];
#pragma unroll
    for (int r = 0; r < 4; r++) {
        int lin = tid + (r << 8);
        bk[r] = lin >> 5;
        int n4 = (lin & 31) << 2;
        bcol[r] = G1 ? ((n4 < 64) ? base_n + n4 : DFF - 64 + base_n + n4) : base_n + n4;
        bsm[r] = bk[r] * 136 + n4;
    }
    const size_t wqb = (size_t)e * KTOT * NW;
    const size_t wsb = (size_t)e * (KTOT / 128) * NW;

    uint4 stA0, stA1; int4 stB[4];
    auto LOAD = [&](int k0) {
        const uint4* ap = (const uint4*)(Asrc + k0 + aseg * 16);
        stA0 = ap[0]; stA1 = ap[1];
#pragma unroll
        for (int r = 0; r < 4; r++)
            stB[r] = *(const int4*)(wq + wqb + (size_t)(k0 + bk[r]) * NW + bcol[r]);
    };
    auto STORE = [&](int k0, int s) {
        *(uint4*)&sA[s][arow * 40 + aseg * 16]     = stA0;
        *(uint4*)&sA[s][arow * 40 + aseg * 16 + 8] = stA1;
        const int g = k0 >> 7;
#pragma unroll
        for (int r = 0; r < 4; r++) {
            const float4 sc = *(const float4*)(ws + wsb + (size_t)g * NW + bcol[r]);
            __half2 lo = __floats2half2_rn((float)(stB[r].x - 8) * sc.x,
                                           (float)(stB[r].y - 8) * sc.y);
            __half2 hi = __floats2half2_rn((float)(stB[r].z - 8) * sc.z,
                                           (float)(stB[r].w - 8) * sc.w);
            uint2 v; v.x = *(const uint32_t*)&lo; v.y = *(const uint32_t*)&hi;
            *(uint2*)&sB[s][bsm[r]] = v;          // STS.64, conflict-free
        }
    };

    const uint32_t aoff = (uint32_t)(((wm * 64 + lrow) * 40 + lcol) * 2);
    const uint32_t boff = (uint32_t)((lrow * 136 + lcol) * 2);
    // warp n-subtile bases: G1 interleaves gate (p=0) / up (p=1) into the same warp
    const int n0_0 = G1 ? wn * 16      : wn * 32;
    const int n0_1 = G1 ? wn * 16 + 64 : wn * 32 + 16;

    LOAD(0); STORE(0, 0); __syncthreads();
    for (int c = 0; c < NC; c++) {
        const int s = c & 1;
        if (c + 1 < NC) LOAD((c + 1) * 32);
        const uint32_t aS = smem_u32(&sA[s][0]) + aoff;
        const uint32_t bS = smem_u32(&sB[s][0]) + boff;
#pragma unroll
        for (int ks = 0; ks < 2; ks++) {
            uint32_t A[4][4], B0[4], B1[4];
#pragma unroll
            for (int mf = 0; mf < 4; mf++) ldsm4(A[mf], aS + mf * 1280 + ks * 32);
            ldsm4t(B0, bS + ks * 4352 + n0_0 * 2);
            ldsm4t(B1, bS + ks * 4352 + n0_1 * 2);
#pragma unroll
            for (int mf = 0; mf < 4; mf++) {
                mma16816(acc[mf][0], A[mf], &B0[0]);
                mma16816(acc[mf][1], A[mf], &B0[2]);
                mma16816(acc[mf][2], A[mf], &B1[0]);
                mma16816(acc[mf][3], A[mf], &B1[2]);
            }
        }
        if (c + 1 < NC) STORE((c + 1) * 32, (c + 1) & 1);
        __syncthreads();
    }

    // ---- epilogue ----
    if (G1) {
        // gate = acc[.][0..1] (cols wn*16+t*8), up = acc[.][2..3] (cols 64+wn*16+t*8)
#pragma unroll
        for (int mf = 0; mf < 4; mf++)
#pragma unroll
            for (int t = 0; t < 2; t++)
#pragma unroll
                for (int h = 0; h < 2; h++) {
                    int r = row0 + wm * 64 + mf * 16 + qr + h * 8;
                    int f = base_n + wn * 16 + t * 8 + qc;
                    float g0 = acc[mf][t][h * 2 + 0], g1 = acc[mf][t][h * 2 + 1];
                    float u0 = acc[mf][t + 2][h * 2 + 0], u1 = acc[mf][t + 2][h * 2 + 1];
                    float a0 = g0 / (1.f + __expf(-g0)) * u0;
                    float a1 = g1 / (1.f + __expf(-g1)) * u1;
                    *(__half2*)(g_act + (size_t)r * DFF + f) = __floats2half2_rn(a0, a1);
                }
    } else {
#pragma unroll
        for (int mf = 0; mf < 4; mf++)
#pragma unroll
            for (int nf = 0; nf < 4; nf++)
#pragma unroll
                for (int h = 0; h < 2; h++) {
                    int rl = wm * 64 + mf * 16 + qr + h * 8;
                    float cf = sCoef[rl];
                    int col = base_n + wn * 32 + (nf >> 1) * 16 + (nf & 1) * 8 + qc;
                    *(float2*)(g_y + (size_t)(row0 + rl) * DM + col) =
                        make_float2(cf * acc[mf][nf][h * 2 + 0], cf * acc[mf][nf][h * 2 + 1]);
                }
    }
}

// ---------------- gather: out[tok] = y[row0(tok)] + y[row1(tok)] ----------------
__global__ void gather_kernel(float4* __restrict__ out4) {
    int i = blockIdx.x * 256 + threadIdx.x;   // 4096 tok * 256 float4
    int t = i >> 8, c = i & 255;
    int r0 = g_tok2row[t * 2 + 0], r1 = g_tok2row[t * 2 + 1];
    float4 a = ((const float4*)(g_y + (size_t)r0 * DM))[c];
    float4 b = ((const float4*)(g_y + (size_t)r1 * DM))[c];
    out4[i] = make_float4(a.x + b.x, a.y + b.y, a.z + b.z, a.w + b.w);
}

// ---------------- launch ----------------
extern "C" void kernel_launch(void* const* d_in, const int* in_sizes, int n_in,
                              void* d_out, int out_size) {
    const float* x   = (const float*)d_in[0];
    const float* gt  = (const float*)d_in[1];
    const int*   w1q = (const int*)d_in[2];
    const int*   w2q = (const int*)d_in[3];
    const float* w1s = (const float*)d_in[4];
    const float* w2s = (const float*)d_in[5];

    prep_kernel<<<(NTOK * DM / 4) / 256, 256>>>((const float4*)x);
    routing_kernel<<<1, 1024>>>(gt);
    gemm_kernel<true ><<<dim3(MAXT, DFF / 64), 256>>>(w1q, w1s);
    gemm_kernel<false><<<dim3(MAXT, DM / 128), 256>>>(w2q, w2s);
    gather_kernel<<<(NTOK * DM / 4) / 256, 256>>>((float4*)d_out);
}